// round 4
// baseline (speedup 1.0000x reference)
#include <cuda_runtime.h>

#define EPSF 1e-6f
#define S 32
#define C 3
#define K 2          // tiles per warp, packed into f32x2 lanes
#define TILE (S * S) // 1024
#define WARPS_PER_CTA 4

// Precomputed Thomas factorizations, 11 time-indices (j=0..5 x-dir, 6..10 y-dir):
//   g_cf2[(j*C+c)*TILE + i*S + r] = (invd, w)   -- forward sweep
//   g_cw [(j*C+c)*TILE + i*S + r] = w           -- backward sweep reload (compact, L1-hot)
// c_star = -w, so backward sweep is x_i = d_i + w_i * x_{i+1}.
__device__ float2 g_cf2[11 * C * TILE];
__device__ float  g_cw [11 * C * TILE];

// ---------------------------------------------------------------------------
// packed f32x2 helpers (PTX-only; ptxas never auto-fuses)
// ---------------------------------------------------------------------------
__device__ __forceinline__ float2 fma2(float2 a, float2 b, float2 c) {
    unsigned long long au = *reinterpret_cast<unsigned long long*>(&a);
    unsigned long long bu = *reinterpret_cast<unsigned long long*>(&b);
    unsigned long long cu = *reinterpret_cast<unsigned long long*>(&c);
    unsigned long long du;
    asm("fma.rn.f32x2 %0, %1, %2, %3;" : "=l"(du) : "l"(au), "l"(bu), "l"(cu));
    return *reinterpret_cast<float2*>(&du);
}
__device__ __forceinline__ float2 mul2(float2 a, float2 b) {
    unsigned long long au = *reinterpret_cast<unsigned long long*>(&a);
    unsigned long long bu = *reinterpret_cast<unsigned long long*>(&b);
    unsigned long long du;
    asm("mul.rn.f32x2 %0, %1, %2;" : "=l"(du) : "l"(au), "l"(bu));
    return *reinterpret_cast<float2*>(&du);
}

// ---------------------------------------------------------------------------
// Precompute kernel: one thread per (timeIdx, c, row). 11*3*32 = 1056 threads.
// ---------------------------------------------------------------------------
__global__ void precompute_kernel(const float* __restrict__ ab,
                                  const float* __restrict__ bb,
                                  const float* __restrict__ atc,
                                  const float* __restrict__ btc) {
    int tid = blockIdx.x * blockDim.x + threadIdx.x;
    if (tid >= 11 * C * S) return;
    int j   = tid / (C * S);
    int rem = tid % (C * S);
    int c   = rem / S;
    int r   = rem % S;

    float t, fac;
    const float* bp;
    const float* tp;
    int stride;
    if (j < 6) {                       // x-direction, t = j*DT, dt = DT/2
        t   = (float)(j * 0.1);
        fac = 0.05f;
        bp  = ab + (c * S + r) * S;
        tp  = atc + (c * S + r) * S;
        stride = 1;
    } else {                           // y-direction, t = DT/2 + jy*DT, dt = DT
        int jy = j - 6;
        t   = (float)(0.05 + jy * 0.1);
        fac = 0.1f;
        bp  = bb + c * TILE + r;
        tp  = btc + c * TILE + r;
        stride = S;
    }
    float2* out2 = g_cf2 + (j * C + c) * TILE;
    float*  outw = g_cw  + (j * C + c) * TILE;

    float coef[S];
#pragma unroll
    for (int i = 0; i < S; ++i)
        coef[i] = fmaxf(bp[i * stride] + t * tp[i * stride], EPSF);

    float cs[S];
    cs[0] = (coef[0] + coef[0] + coef[1]) / 3.0f * fac;
#pragma unroll
    for (int i = 1; i < S - 1; ++i)
        cs[i] = (coef[i - 1] + coef[i] + coef[i + 1]) / 3.0f * fac;
    cs[S - 1] = (coef[S - 2] + coef[S - 1] + coef[S - 1]) / 3.0f * fac;

    float wprev = 0.0f;
#pragma unroll
    for (int i = 0; i < S; ++i) {
        float b = 1.0f + 2.0f * cs[i];
        if (i == 0)     b = 1.0f + cs[0];
        if (i == S - 1) b = 1.0f + cs[S - 1];
        float denom = b - cs[i] * wprev + EPSF;
        float invd  = 1.0f / denom;
        float w     = cs[i] * invd;
        out2[i * S + r] = make_float2(invd, w);
        outw[i * S + r] = w;
        wprev = w;
    }
}

// ---------------------------------------------------------------------------
// Main fused ADI kernel: 4 warps/CTA (all same channel c), K=2 tiles per warp
// packed in f32x2. v[i] = (tile0, tile1) for row `lane`, position i.
// ---------------------------------------------------------------------------
__global__ __launch_bounds__(32 * WARPS_PER_CTA, 4)
void adi_kernel(const float* __restrict__ uin, float* __restrict__ uout) {
    __shared__ float smbuf[WARPS_PER_CTA * S * 33];
    const int lane = threadIdx.x & 31;
    const int wip  = threadIdx.x >> 5;
    float* sm = smbuf + wip * (S * 33);

    // all warps in a CTA share channel c (coefficient L1 locality)
    const int cid = blockIdx.x % C;
    const int grp = blockIdx.x / C;                     // 0..255
    const int bg  = grp * WARPS_PER_CTA + wip;          // 0..1023
    const int base0 = (bg * K) * C * TILE + cid * TILE; // tile k at +k*C*TILE

    float2 v[S];   // packed across the 2 tiles

    // ---- load: gmem (coalesced) -> smem -> regs (lane = row h) ----
#pragma unroll
    for (int k = 0; k < K; ++k) {
        const int tb = base0 + k * C * TILE;
        __syncwarp();
#pragma unroll
        for (int r = 0; r < S; ++r)
            sm[r * 33 + lane] = uin[tb + r * S + lane];
        __syncwarp();
        if (k == 0) {
#pragma unroll
            for (int i = 0; i < S; ++i) v[i].x = sm[lane * 33 + i];
        } else {
#pragma unroll
            for (int i = 0; i < S; ++i) v[i].y = sm[lane * 33 + i];
        }
    }
    __syncwarp();

    // ---- Thomas solve: fwd uses (invd,w) float2; bwd reloads w (L1-hot) ----
    auto solve = [&](int j) {
        const float2* __restrict__ cf2 = g_cf2 + (j * C + cid) * TILE;
        const float*  __restrict__ cw  = g_cw  + (j * C + cid) * TILE;
        float2 dprev = make_float2(0.0f, 0.0f);
#pragma unroll
        for (int i = 0; i < S; ++i) {
            float2 iw = __ldg(&cf2[i * S + lane]);
            float2 t = mul2(v[i], make_float2(iw.x, iw.x));
            t = fma2(make_float2(iw.y, iw.y), dprev, t);
            v[i] = t;
            dprev = t;
        }
#pragma unroll
        for (int i = S - 2; i >= 0; --i) {
            float w = __ldg(&cw[i * S + lane]);
            v[i] = fma2(make_float2(w, w), v[i + 1], v[i]);
        }
    };

    // ---- 32x32 transpose via padded smem, one component at a time ----
    auto transpose = [&]() {
        __syncwarp();
#pragma unroll
        for (int i = 0; i < S; ++i) sm[lane * 33 + i] = v[i].x;
        __syncwarp();
#pragma unroll
        for (int i = 0; i < S; ++i) v[i].x = sm[i * 33 + lane];
        __syncwarp();
#pragma unroll
        for (int i = 0; i < S; ++i) sm[lane * 33 + i] = v[i].y;
        __syncwarp();
#pragma unroll
        for (int i = 0; i < S; ++i) v[i].y = sm[i * 33 + lane];
        __syncwarp();
    };

    // substep sequence: X0 | [T Y_it T X_{it+1} (X_{it+1} again if it<4)]
    solve(0);
#pragma unroll 1
    for (int it = 0; it < 5; ++it) {
        transpose();
        solve(6 + it);          // y-direction table
        transpose();
        solve(it + 1);          // x-direction
        if (it < 4) solve(it + 1);
    }

    // ---- store: regs -> smem -> gmem (coalesced) ----
#pragma unroll
    for (int k = 0; k < K; ++k) {
        const int tb = base0 + k * C * TILE;
        __syncwarp();
        if (k == 0) {
#pragma unroll
            for (int i = 0; i < S; ++i) sm[lane * 33 + i] = v[i].x;
        } else {
#pragma unroll
            for (int i = 0; i < S; ++i) sm[lane * 33 + i] = v[i].y;
        }
        __syncwarp();
#pragma unroll
        for (int r = 0; r < S; ++r)
            uout[tb + r * S + lane] = sm[r * 33 + lane];
    }
}

// ---------------------------------------------------------------------------
extern "C" void kernel_launch(void* const* d_in, const int* in_sizes, int n_in,
                              void* d_out, int out_size) {
    const float* u   = (const float*)d_in[0];
    const float* ab  = (const float*)d_in[1];
    const float* bb  = (const float*)d_in[2];
    const float* atc = (const float*)d_in[3];
    const float* btc = (const float*)d_in[4];
    float* out = (float*)d_out;

    const int B = in_sizes[0] / (C * TILE);         // 2048

    precompute_kernel<<<(11 * C * S + 127) / 128, 128>>>(ab, bb, atc, btc);

    const int nwarps = (B / K) * C;                 // 3072 warps
    adi_kernel<<<nwarps / WARPS_PER_CTA, 32 * WARPS_PER_CTA>>>(u, out);
}

// round 5
// speedup vs baseline: 1.8378x; 1.8378x over previous
#include <cuda_runtime.h>

#define EPSF 1e-6f
#define S 32
#define C 3
#define TILE (S * S)   // 1024
#define WPC 2          // warps per CTA (64 threads)

// Precomputed Thomas factorizations, 11 time-indices (j=0..5 x-dir, 6..10 y-dir):
//   g_cf2[(j*C+c)*TILE + i*S + r] = (invd, w)
// c_star = -w, so backward sweep is x_i = d_i + w_i * x_{i+1}.
__device__ float2 g_cf2[11 * C * TILE];

// solve order over the 15 substeps, as j-indices into g_cf2
__constant__ int c_jseq[15] = {0, 6, 1, 1, 7, 2, 2, 8, 3, 3, 9, 4, 4, 10, 5};

// ---------------------------------------------------------------------------
// packed f32x2 helpers (PTX-only; ptxas never auto-fuses)
// ---------------------------------------------------------------------------
__device__ __forceinline__ float2 fma2(float2 a, float2 b, float2 c) {
    unsigned long long au = *reinterpret_cast<unsigned long long*>(&a);
    unsigned long long bu = *reinterpret_cast<unsigned long long*>(&b);
    unsigned long long cu = *reinterpret_cast<unsigned long long*>(&c);
    unsigned long long du;
    asm("fma.rn.f32x2 %0, %1, %2, %3;" : "=l"(du) : "l"(au), "l"(bu), "l"(cu));
    return *reinterpret_cast<float2*>(&du);
}
__device__ __forceinline__ float2 mul2(float2 a, float2 b) {
    unsigned long long au = *reinterpret_cast<unsigned long long*>(&a);
    unsigned long long bu = *reinterpret_cast<unsigned long long*>(&b);
    unsigned long long du;
    asm("mul.rn.f32x2 %0, %1, %2;" : "=l"(du) : "l"(au), "l"(bu));
    return *reinterpret_cast<float2*>(&du);
}
__device__ __forceinline__ void pf_l1(const void* p) {
    asm volatile("prefetch.global.L1 [%0];" :: "l"(p));
}

// ---------------------------------------------------------------------------
// Precompute kernel: one thread per (timeIdx, c, row). 11*3*32 = 1056 threads.
// ---------------------------------------------------------------------------
__global__ void precompute_kernel(const float* __restrict__ ab,
                                  const float* __restrict__ bb,
                                  const float* __restrict__ atc,
                                  const float* __restrict__ btc) {
    int tid = blockIdx.x * blockDim.x + threadIdx.x;
    if (tid >= 11 * C * S) return;
    int j   = tid / (C * S);
    int rem = tid % (C * S);
    int c   = rem / S;
    int r   = rem % S;

    float t, fac;
    const float* bp;
    const float* tp;
    int stride;
    if (j < 6) {                       // x-direction, t = j*DT, dt = DT/2
        t   = (float)(j * 0.1);
        fac = 0.05f;
        bp  = ab + (c * S + r) * S;
        tp  = atc + (c * S + r) * S;
        stride = 1;
    } else {                           // y-direction, t = DT/2 + jy*DT, dt = DT
        int jy = j - 6;
        t   = (float)(0.05 + jy * 0.1);
        fac = 0.1f;
        bp  = bb + c * TILE + r;
        tp  = btc + c * TILE + r;
        stride = S;
    }
    float2* out2 = g_cf2 + (j * C + c) * TILE;

    float coef[S];
#pragma unroll
    for (int i = 0; i < S; ++i)
        coef[i] = fmaxf(bp[i * stride] + t * tp[i * stride], EPSF);

    float cs[S];
    cs[0] = (coef[0] + coef[0] + coef[1]) / 3.0f * fac;
#pragma unroll
    for (int i = 1; i < S - 1; ++i)
        cs[i] = (coef[i - 1] + coef[i] + coef[i + 1]) / 3.0f * fac;
    cs[S - 1] = (coef[S - 2] + coef[S - 1] + coef[S - 1]) / 3.0f * fac;

    float wprev = 0.0f;
#pragma unroll
    for (int i = 0; i < S; ++i) {
        float b = 1.0f + 2.0f * cs[i];
        if (i == 0)     b = 1.0f + cs[0];
        if (i == S - 1) b = 1.0f + cs[S - 1];
        float denom = b - cs[i] * wprev + EPSF;
        float invd  = 1.0f / denom;
        float w     = cs[i] * invd;
        out2[i * S + r] = make_float2(invd, w);
        wprev = w;
    }
}

// ---------------------------------------------------------------------------
// Main fused ADI kernel: 2 warps/CTA (same channel c), 2 tiles per warp
// packed in f32x2. v[i] = (tile0, tile1) element at (row=lane, pos=i).
// ---------------------------------------------------------------------------
__global__ __launch_bounds__(32 * WPC, 6)
void adi_kernel(const float* __restrict__ uin, float* __restrict__ uout) {
    __shared__ float2 slab[WPC][S * 33];
    const int lane = threadIdx.x & 31;
    const int wip  = threadIdx.x >> 5;
    float2* sm = slab[wip];
    float*  smf = reinterpret_cast<float*>(sm);

    const int cid = blockIdx.x % C;
    const int grp = blockIdx.x / C;                 // 0..511
    const int bg  = grp * WPC + wip;                // batch-pair index 0..1023
    const int base0 = (2 * bg) * C * TILE + cid * TILE;   // tile k at +k*C*TILE

    float2 v[S];     // packed over 2 tiles
    float  warr[S];

    // ---- load: gmem (coalesced) -> smem component k -> regs (lane = row) ----
#pragma unroll
    for (int k = 0; k < 2; ++k) {
        const int tb = base0 + k * C * TILE;
#pragma unroll
        for (int r = 0; r < S; ++r)
            smf[2 * (r * 33 + lane) + k] = uin[tb + r * S + lane];
    }
    __syncwarp();
#pragma unroll
    for (int i = 0; i < S; ++i)
        v[i] = sm[lane * 33 + i];
    __syncwarp();

    // ---- Thomas solve; cf = this solve's table, nf = next solve's (prefetch)
    auto solve = [&](const float2* __restrict__ cf, const float2* nf) {
        // prefetch next solve's 8KB table into L1 (64 lines, 2 instrs)
        if (nf) {
            const char* p = (const char*)nf + lane * 128;
            pf_l1(p);
            pf_l1(p + 4096);
        }
        // forward sweep, blocked 2-stage coefficient pipeline
        float2 cb[2][8];
#pragma unroll
        for (int m = 0; m < 8; ++m)
            cb[0][m] = __ldg(&cf[m * S + lane]);
        float2 dprev = make_float2(0.0f, 0.0f);
#pragma unroll
        for (int blk = 0; blk < 4; ++blk) {
            if (blk < 3) {
#pragma unroll
                for (int m = 0; m < 8; ++m)
                    cb[(blk + 1) & 1][m] = __ldg(&cf[((blk + 1) * 8 + m) * S + lane]);
            }
#pragma unroll
            for (int m = 0; m < 8; ++m) {
                const int i = blk * 8 + m;
                float2 iw = cb[blk & 1][m];
                warr[i] = iw.y;
                float2 t = mul2(v[i], make_float2(iw.x, iw.x));
                t = fma2(make_float2(iw.y, iw.y), dprev, t);
                v[i] = t;
                dprev = t;
            }
        }
        // backward sweep (w in registers -> pure 4-cyc chain)
#pragma unroll
        for (int i = S - 2; i >= 0; --i)
            v[i] = fma2(make_float2(warr[i], warr[i]), v[i + 1], v[i]);
    };

    // ---- 32x32 transpose via padded float2 smem (conflict-free 64-bit) ----
    auto transpose = [&]() {
        __syncwarp();
#pragma unroll
        for (int i = 0; i < S; ++i) sm[lane * 33 + i] = v[i];
        __syncwarp();
#pragma unroll
        for (int i = 0; i < S; ++i) v[i] = sm[i * 33 + lane];
        __syncwarp();
    };

    const float2* tab = g_cf2 + cid * TILE;   // + j*C*TILE per time index

    // 15 substeps: X0 Y0 X1 X1 Y1 X2 X2 Y2 X3 X3 Y3 X4 X4 Y4 X5
#pragma unroll 1
    for (int s = 0; s < 15; ++s) {
        const int j  = c_jseq[s];
        const int jn = (s < 14) ? c_jseq[s + 1] : -1;
        const float2* nf = (jn >= 0) ? (tab + jn * C * TILE) : (const float2*)0;
        solve(tab + j * C * TILE, nf);
        if (jn >= 0 && ((j < 6) != (jn < 6)))
            transpose();
    }

    // ---- store: regs -> smem -> gmem (coalesced) ----
    __syncwarp();
#pragma unroll
    for (int i = 0; i < S; ++i) sm[lane * 33 + i] = v[i];
    __syncwarp();
#pragma unroll
    for (int k = 0; k < 2; ++k) {
        const int tb = base0 + k * C * TILE;
#pragma unroll
        for (int r = 0; r < S; ++r)
            uout[tb + r * S + lane] = smf[2 * (r * 33 + lane) + k];
    }
}

// ---------------------------------------------------------------------------
extern "C" void kernel_launch(void* const* d_in, const int* in_sizes, int n_in,
                              void* d_out, int out_size) {
    const float* u   = (const float*)d_in[0];
    const float* ab  = (const float*)d_in[1];
    const float* bb  = (const float*)d_in[2];
    const float* atc = (const float*)d_in[3];
    const float* btc = (const float*)d_in[4];
    float* out = (float*)d_out;

    const int B = in_sizes[0] / (C * TILE);         // 2048

    precompute_kernel<<<(11 * C * S + 127) / 128, 128>>>(ab, bb, atc, btc);

    const int npairs = B / 2;                        // 1024 batch-pairs
    const int nwarps = npairs * C;                   // 3072 warps
    adi_kernel<<<nwarps / WPC, 32 * WPC>>>(u, out);
}